// round 14
// baseline (speedup 1.0000x reference)
#include <cuda_runtime.h>
#include <cstdint>
#include <math.h>

constexpr int B  = 16;
constexpr int C  = 256;
constexpr int HW = 4096;
constexpr int D  = 32;

constexpr int MT = 64;
constexpr int NT = 32;
constexpr int NTILES = HW / NT;   // 128

__device__ float g_q[B * HW * 64];  // [b][n][kperm(d) | 32+kperm(d)] = tf32 hi|lo
__device__ float g_k[B * HW * D];   // [b][m][d] fp32 plain
__device__ float g_v[B * HW * C];   // [b][tile][e][kperm(k)] tf32, tile-major

__device__ __forceinline__ uint32_t to_tf32_bits(float x) {
    uint32_t r;
    asm("cvt.rna.tf32.f32 %0, %1;" : "=r"(r) : "f"(x));
    return r;
}

__device__ __forceinline__ void mma_tf32_16x8x8(
    float& c0, float& c1, float& c2, float& c3,
    uint32_t a0, uint32_t a1, uint32_t a2, uint32_t a3,
    uint32_t b0, uint32_t b1)
{
    asm volatile(
        "mma.sync.aligned.m16n8k8.row.col.f32.tf32.tf32.f32 "
        "{%0,%1,%2,%3}, {%4,%5,%6,%7}, {%8,%9}, {%0,%1,%2,%3};"
        : "+f"(c0), "+f"(c1), "+f"(c2), "+f"(c3)
        : "r"(a0), "r"(a1), "r"(a2), "r"(a3), "r"(b0), "r"(b1));
}

__device__ __forceinline__ uint32_t smem_u32(const void* p) {
    uint32_t a;
    asm("{ .reg .u64 t; cvta.to.shared.u64 t, %1; cvt.u32.u64 %0, t; }"
        : "=r"(a) : "l"(p));
    return a;
}
#define CP_ASYNC8(dst, src) \
    asm volatile("cp.async.ca.shared.global [%0], [%1], 8;" :: "r"(dst), "l"(src))
#define CP_COMMIT() asm volatile("cp.async.commit_group;" ::: "memory")
#define CP_WAIT0()  asm volatile("cp.async.wait_group 0;"  ::: "memory")

__device__ __forceinline__ int kperm(int k) {
    return ((k & 3) << 3) + ((k >> 3) << 1) + ((k >> 2) & 1);
}
__device__ __forceinline__ int kinv(int d) {
    return (d >> 3) + ((d & 1) << 2) + (((d >> 1) & 3) << 3);
}

// ===========================================================================
// Projection GEMMs
// ===========================================================================
__global__ __launch_bounds__(256) void proj_kernel(
    const float* __restrict__ x, const float* __restrict__ W,
    float* __restrict__ out, int Etot)
{
    constexpr int BN = 128, KC = 32;
    __shared__ __align__(16) float Xs[KC][BN + 4];
    __shared__ float Ws[KC][33];
    const int b = blockIdx.y, n0 = blockIdx.x * BN, e0 = blockIdx.z * 32;
    const int tid = threadIdx.x, tn = tid & 31, te = tid >> 5;
    float acc[4][4] = {};
    const float* xb = x + (size_t)b * C * HW;
    for (int c0 = 0; c0 < C; c0 += KC) {
        #pragma unroll
        for (int r = 0; r < 4; r++) {
            int idx = tid + 256 * r;
            int c = idx >> 5, n4 = (idx & 31) * 4;
            *(float4*)&Xs[c][n4] = *(const float4*)&xb[(size_t)(c0 + c) * HW + n0 + n4];
        }
        {
            int e = tid >> 3, c4 = (tid & 7) * 4;
            float4 w4 = *(const float4*)&W[(size_t)(e0 + e) * C + c0 + c4];
            Ws[c4 + 0][e] = w4.x; Ws[c4 + 1][e] = w4.y;
            Ws[c4 + 2][e] = w4.z; Ws[c4 + 3][e] = w4.w;
        }
        __syncthreads();
        #pragma unroll
        for (int c = 0; c < KC; c++) {
            float4 xa = *(const float4*)&Xs[c][tn * 4];
            float xv[4] = {xa.x, xa.y, xa.z, xa.w};
            float wb[4];
            #pragma unroll
            for (int j = 0; j < 4; j++) wb[j] = Ws[c][te * 4 + j];
            #pragma unroll
            for (int i = 0; i < 4; i++)
                #pragma unroll
                for (int j = 0; j < 4; j++)
                    acc[i][j] = fmaf(xv[i], wb[j], acc[i][j]);
        }
        __syncthreads();
    }
    #pragma unroll
    for (int i = 0; i < 4; i++) {
        float4 o4 = make_float4(acc[i][0], acc[i][1], acc[i][2], acc[i][3]);
        int n = n0 + tn * 4 + i;
        *(float4*)&out[((size_t)b * HW + n) * Etot + e0 + te * 4] = o4;
    }
}

// q projection: PRE-SPLIT tf32 hi/lo, d-interleaved: out[b][n][kperm(d)] = hi,
// out[b][n][32 + kperm(d)] = lo.
__global__ __launch_bounds__(256) void proj_kernel_QI(
    const float* __restrict__ x, const float* __restrict__ W,
    float* __restrict__ out)
{
    constexpr int BN = 128, KC = 32;
    __shared__ __align__(16) float Xs[KC][BN + 4];
    __shared__ float Ws[KC][33];
    const int b = blockIdx.y, n0 = blockIdx.x * BN;
    const int tid = threadIdx.x, tn = tid & 31, te = tid >> 5;
    float acc[4][4] = {};
    const float* xb = x + (size_t)b * C * HW;
    for (int c0 = 0; c0 < C; c0 += KC) {
        #pragma unroll
        for (int r = 0; r < 4; r++) {
            int idx = tid + 256 * r;
            int c = idx >> 5, n4 = (idx & 31) * 4;
            *(float4*)&Xs[c][n4] = *(const float4*)&xb[(size_t)(c0 + c) * HW + n0 + n4];
        }
        {
            int e = tid >> 3, c4 = (tid & 7) * 4;
            float4 w4 = *(const float4*)&W[(size_t)e * C + c0 + c4];
            Ws[c4 + 0][e] = w4.x; Ws[c4 + 1][e] = w4.y;
            Ws[c4 + 2][e] = w4.z; Ws[c4 + 3][e] = w4.w;
        }
        __syncthreads();
        #pragma unroll
        for (int c = 0; c < KC; c++) {
            float4 xa = *(const float4*)&Xs[c][tn * 4];
            float xv[4] = {xa.x, xa.y, xa.z, xa.w};
            float wb[4];
            #pragma unroll
            for (int j = 0; j < 4; j++) wb[j] = Ws[c][te * 4 + j];
            #pragma unroll
            for (int i = 0; i < 4; i++)
                #pragma unroll
                for (int j = 0; j < 4; j++)
                    acc[i][j] = fmaf(xv[i], wb[j], acc[i][j]);
        }
        __syncthreads();
    }
    #pragma unroll
    for (int i = 0; i < 4; i++) {
        int n = n0 + tn * 4 + i;
        float* orow = &out[((size_t)b * HW + n) * 64];
        #pragma unroll
        for (int j = 0; j < 4; j++) {
            int kp = kperm(te * 4 + j);
            uint32_t hb = to_tf32_bits(acc[i][j]);
            float hi = __uint_as_float(hb);
            orow[kp]      = hi;
            orow[32 + kp] = __uint_as_float(to_tf32_bits(acc[i][j] - hi));
        }
    }
}

// V projection: tf32-rounded, tile-major interleaved (unchanged from r13).
__global__ __launch_bounds__(256) void proj_kernel_T(
    const float* __restrict__ x, const float* __restrict__ W,
    float* __restrict__ out, int Etot)
{
    constexpr int BN = 128, KC = 32;
    __shared__ __align__(16) float Xs[KC][BN + 4];
    __shared__ float Ws[KC][33];
    const int b = blockIdx.y, n0 = blockIdx.x * BN, e0 = blockIdx.z * 32;
    const int tid = threadIdx.x, tn = tid & 31, te = tid >> 5;
    float acc[4][4] = {};
    const float* xb = x + (size_t)b * C * HW;
    for (int c0 = 0; c0 < C; c0 += KC) {
        #pragma unroll
        for (int r = 0; r < 4; r++) {
            int idx = tid + 256 * r;
            int c = idx >> 5, n4 = (idx & 31) * 4;
            *(float4*)&Xs[c][n4] = *(const float4*)&xb[(size_t)(c0 + c) * HW + n0 + n4];
        }
        {
            int e = tid >> 3, c4 = (tid & 7) * 4;
            float4 w4 = *(const float4*)&W[(size_t)(e0 + e) * C + c0 + c4];
            Ws[c4 + 0][e] = w4.x; Ws[c4 + 1][e] = w4.y;
            Ws[c4 + 2][e] = w4.z; Ws[c4 + 3][e] = w4.w;
        }
        __syncthreads();
        #pragma unroll
        for (int c = 0; c < KC; c++) {
            float4 xa = *(const float4*)&Xs[c][tn * 4];
            float xv[4] = {xa.x, xa.y, xa.z, xa.w};
            float wb[4];
            #pragma unroll
            for (int j = 0; j < 4; j++) wb[j] = Ws[c][te * 4 + j];
            #pragma unroll
            for (int i = 0; i < 4; i++)
                #pragma unroll
                for (int j = 0; j < 4; j++)
                    acc[i][j] = fmaf(xv[i], wb[j], acc[i][j]);
        }
        __syncthreads();
    }
    #pragma unroll
    for (int j = 0; j < 4; j++) {
        *(float4*)&Xs[te * 4 + j][tn * 4] = make_float4(
            __uint_as_float(to_tf32_bits(acc[0][j])),
            __uint_as_float(to_tf32_bits(acc[1][j])),
            __uint_as_float(to_tf32_bits(acc[2][j])),
            __uint_as_float(to_tf32_bits(acc[3][j])));
    }
    __syncthreads();
    const int e_loc = tid >> 3;
    const int dbase = (tid & 7) * 4;
    const int t0 = n0 / 32;
    #pragma unroll
    for (int blk = 0; blk < 4; blk++) {
        const float* srow = &Xs[e_loc][blk * 32];
        float4 o;
        o.x = srow[kinv(dbase + 0)];
        o.y = srow[kinv(dbase + 1)];
        o.z = srow[kinv(dbase + 2)];
        o.w = srow[kinv(dbase + 3)];
        *(float4*)&out[(((size_t)b * NTILES + t0 + blk) * C + e0 + e_loc) * 32 + dbase] = o;
    }
}

// ===========================================================================
// Flash attention: 512 threads (16 warps), CTA 64m x 128e (e-half in grid.z).
// Per-warp: S = one m16n8 tile (pre-split q, 8 MMAs); PV = 16m x 32e (16 MMAs,
// acc 16 regs). Same chip tensor work as r13, 2x warps for latency hiding.
// ===========================================================================
constexpr int ST_PV  = 34;   // Ps/Vs row stride
constexpr int ST_Q   = 66;   // q rows: 32 hi + 32 lo + 2 pad
constexpr int ST_STG = 130;

constexpr int Q_STRIDE  = 32 * ST_Q;     // 2112
constexpr int PS_STRIDE = 64 * ST_PV;    // 2176
constexpr int VS_STRIDE = 128 * ST_PV;   // 4352

constexpr int QS_OFF  = 0;                        // 2 x [32][66]
constexpr int PS_OFF  = QS_OFF + 2 * Q_STRIDE;    // 2 x [64][34]
constexpr int INV_OFF = PS_OFF + 2 * PS_STRIDE;   // [64]
constexpr int VS_OFF  = INV_OFF + 64;             // 2 x [128][34] (Stage overlays)
constexpr int FLASH_FLOATS = VS_OFF + 2 * VS_STRIDE;   // 17344
constexpr int FLASH_SMEM = FLASH_FLOATS * 4;           // 69376 B

__global__ __launch_bounds__(512, 2) void flash_kernel(
    const float* __restrict__ x, const float* __restrict__ gamma_p,
    float* __restrict__ out)
{
    extern __shared__ __align__(16) float sm[];
    float* Qsm   = sm + QS_OFF;
    float* Ps    = sm + PS_OFF;
    float* invs  = sm + INV_OFF;
    float* Vs    = sm + VS_OFF;
    float* Stage = sm + VS_OFF;

    const int tid  = threadIdx.x;
    const int wid  = tid >> 5;          // 0..15
    const int lane = tid & 31;
    const int b    = blockIdx.y;
    const int m0   = blockIdx.x * MT;
    const int ehalf = blockIdx.z;

    const int g  = lane >> 2;
    const int tg = lane & 3;
    const int mbW  = wid & 3;           // S m16-block AND PV m16-block
    const int nbS  = wid >> 2;          // S n8-block (0..3)
    const int pm16 = mbW * 16;          // PV m base
    const int pe   = (wid >> 2) * 32;   // PV e base (0..96)

    if (tid < 64) invs[tid] = 0.0f;

    // Kernel-lifetime K hi-fragments for m16-block mbW.
    uint32_t Ah[4][4];
    {
        const float* kb = g_k + ((size_t)b * HW + m0 + pm16) * D;
        #pragma unroll
        for (int kk = 0; kk < 4; kk++) {
            Ah[kk][0] = to_tf32_bits(kb[g * D + kk * 8 + tg]);
            Ah[kk][1] = to_tf32_bits(kb[(g + 8) * D + kk * 8 + tg]);
            Ah[kk][2] = to_tf32_bits(kb[g * D + kk * 8 + tg + 4]);
            Ah[kk][3] = to_tf32_bits(kb[(g + 8) * D + kk * 8 + tg + 4]);
        }
    }

    float acc[4][4] = {};    // 16m x 32e (4 n8-blocks)
    float rs0 = 0.0f, rs1 = 0.0f;

    // Load thread mappings (512 threads)
    const int vrow = tid >> 2;          // 0..127
    const int vcol = (tid & 3) * 8;     // 8 floats
    const int qrow = tid >> 4;          // 0..31
    const int qcol = (tid & 15) * 4;    // 4 floats

    const float* vptr = g_v + (((size_t)b * NTILES) * C + ehalf * 128 + vrow) * 32 + vcol;
    const float* qptr = g_q + ((size_t)b * HW + qrow) * 64 + qcol;

    const uint32_t sb    = smem_u32(sm);
    const uint32_t vdst0 = sb + (VS_OFF + vrow * ST_PV + vcol) * 4;
    const uint32_t qdst0 = sb + (QS_OFF + qrow * ST_Q + qcol) * 4;

    auto load_tile_async = [&](int bufsel) {
        uint32_t vd = vdst0 + bufsel * (VS_STRIDE * 4);
        CP_ASYNC8(vd,      vptr);
        CP_ASYNC8(vd + 8,  vptr + 2);
        CP_ASYNC8(vd + 16, vptr + 4);
        CP_ASYNC8(vd + 24, vptr + 6);
        uint32_t qd = qdst0 + bufsel * (Q_STRIDE * 4);
        CP_ASYNC8(qd,     qptr);
        CP_ASYNC8(qd + 8, qptr + 2);
        CP_COMMIT();
        vptr += C * 32;     // next tile block
        qptr += NT * 64;
    };

    // S phase: one m16n8 tile (mbW, nbS), pre-split q, 2-term split-tf32.
    auto s_phase = [&](int bufsel) {
        const float* pQ = Qsm + bufsel * Q_STRIDE + (nbS * 8 + g) * ST_Q + 8 * tg;
        float sC[4] = {0.f, 0.f, 0.f, 0.f};
        #pragma unroll
        for (int kk = 0; kk < 4; kk++) {
            float2 qh = *(const float2*)&pQ[2 * kk];
            float2 ql = *(const float2*)&pQ[32 + 2 * kk];
            mma_tf32_16x8x8(sC[0], sC[1], sC[2], sC[3],
                            Ah[kk][0], Ah[kk][1], Ah[kk][2], Ah[kk][3],
                            __float_as_uint(qh.x), __float_as_uint(qh.y));
            mma_tf32_16x8x8(sC[0], sC[1], sC[2], sC[3],
                            Ah[kk][0], Ah[kk][1], Ah[kk][2], Ah[kk][3],
                            __float_as_uint(ql.x), __float_as_uint(ql.y));
        }
        float* Pb = Ps + bufsel * PS_STRIDE;
        const int fl = 16 * (tg & 1) + 2 * nbS + (tg >> 1);
        float p0 = __uint_as_float(to_tf32_bits(__expf(sC[0])));
        float p1 = __uint_as_float(to_tf32_bits(__expf(sC[1])));
        float p2 = __uint_as_float(to_tf32_bits(__expf(sC[2])));
        float p3 = __uint_as_float(to_tf32_bits(__expf(sC[3])));
        const int r0 = pm16 + g;
        Pb[r0 * ST_PV + fl]           = p0;
        Pb[r0 * ST_PV + fl + 8]       = p1;
        Pb[(r0 + 8) * ST_PV + fl]     = p2;
        Pb[(r0 + 8) * ST_PV + fl + 8] = p3;
        rs0 += p0 + p1;
        rs1 += p2 + p3;
    };

    // Prologue
    load_tile_async(0);
    CP_WAIT0();
    __syncthreads();
    s_phase(0);
    load_tile_async(1);

    for (int t = 0; t < NTILES; t++) {
        const int buf = t & 1, nxt = buf ^ 1;
        if (t + 1 < NTILES) CP_WAIT0();
        __syncthreads();   // BAR A

        // PV(t): acc[16m x 32e] += P(t)[16m x 32k] * V(t)[32k x 32e]
        {
            const float* pA = Ps + buf * PS_STRIDE + (pm16 + g) * ST_PV + 8 * tg;
            const float* pB = Vs + buf * VS_STRIDE + (pe + g) * ST_PV + 8 * tg;
            #pragma unroll
            for (int kk = 0; kk < 4; kk++) {
                float2 a0 = *(const float2*)&pA[2 * kk];
                float2 a1 = *(const float2*)&pA[8 * ST_PV + 2 * kk];
                uint32_t ua0 = __float_as_uint(a0.x), ua1 = __float_as_uint(a1.x);
                uint32_t ua2 = __float_as_uint(a0.y), ua3 = __float_as_uint(a1.y);
                #pragma unroll
                for (int nb = 0; nb < 4; nb++) {
                    float2 bb = *(const float2*)&pB[nb * 8 * ST_PV + 2 * kk];
                    mma_tf32_16x8x8(acc[nb][0], acc[nb][1], acc[nb][2], acc[nb][3],
                                    ua0, ua1, ua2, ua3,
                                    __float_as_uint(bb.x), __float_as_uint(bb.y));
                }
            }
        }
        if (t + 1 < NTILES) s_phase(nxt);
        __syncthreads();   // BAR B
        if (t + 2 < NTILES) load_tile_async(buf);
    }

    // rsum combine (4 warps share each mbW; atomics handle it)
    rs0 += __shfl_xor_sync(0xffffffffu, rs0, 1);
    rs0 += __shfl_xor_sync(0xffffffffu, rs0, 2);
    rs1 += __shfl_xor_sync(0xffffffffu, rs1, 1);
    rs1 += __shfl_xor_sync(0xffffffffu, rs1, 2);
    if (tg == 0) {
        atomicAdd(&invs[pm16 + g], rs0);
        atomicAdd(&invs[pm16 + 8 + g], rs1);
    }
    __syncthreads();
    const float gamma = *gamma_p;
    if (tid < 64) invs[tid] = gamma / invs[tid];
    __syncthreads();

    // Epilogue
    {
        const int r0 = pm16 + g;
        const int r1 = r0 + 8;
        const float i0 = invs[r0];
        const float i1 = invs[r1];
        #pragma unroll
        for (int nb = 0; nb < 4; nb++) {
            int col = pe + nb * 8 + tg * 2;
            *(float2*)&Stage[r0 * ST_STG + col] =
                make_float2(acc[nb][0] * i0, acc[nb][1] * i0);
            *(float2*)&Stage[r1 * ST_STG + col] =
                make_float2(acc[nb][2] * i1, acc[nb][3] * i1);
        }
        __syncthreads();
        const int ml  = (lane & 15) * 4;
        const int sub = lane >> 4;
        #pragma unroll
        for (int it = 0; it < 4; it++) {
            int e_loc = it * 32 + wid * 2 + sub;
            int eg = ehalf * 128 + e_loc;
            size_t idx = ((size_t)b * C + eg) * HW + m0 + ml;
            float4 xv = *(const float4*)&x[idx];
            float4 ov;
            ov.x = Stage[(ml + 0) * ST_STG + e_loc] + xv.x;
            ov.y = Stage[(ml + 1) * ST_STG + e_loc] + xv.y;
            ov.z = Stage[(ml + 2) * ST_STG + e_loc] + xv.z;
            ov.w = Stage[(ml + 3) * ST_STG + e_loc] + xv.w;
            *(float4*)&out[idx] = ov;
        }
    }
}

// ===========================================================================
extern "C" void kernel_launch(void* const* d_in, const int* in_sizes, int n_in,
                              void* d_out, int out_size)
{
    const float* x     = (const float*)d_in[0];
    const float* Wq    = (const float*)d_in[1];
    const float* Wk    = (const float*)d_in[2];
    const float* Wv    = (const float*)d_in[3];
    const float* gamma = (const float*)d_in[4];
    float* out = (float*)d_out;

    void *qp, *kp, *vp;
    cudaGetSymbolAddress(&qp, g_q);
    cudaGetSymbolAddress(&kp, g_k);
    cudaGetSymbolAddress(&vp, g_v);

    static bool attr_set = false;
    if (!attr_set) {
        cudaFuncSetAttribute(flash_kernel,
                             cudaFuncAttributeMaxDynamicSharedMemorySize,
                             FLASH_SMEM);
        attr_set = true;
    }

    proj_kernel_QI<<<dim3(HW / 128, B, 1), 256>>>(x, Wq, (float*)qp);
    proj_kernel   <<<dim3(HW / 128, B, 1), 256>>>(x, Wk, (float*)kp, D);
    proj_kernel_T <<<dim3(HW / 128, B, 8), 256>>>(x, Wv, (float*)vp, C);
    flash_kernel<<<dim3(HW / MT, B, 2), 512, FLASH_SMEM>>>(x, gamma, out);
}